// round 1
// baseline (speedup 1.0000x reference)
#include <cuda_runtime.h>
#include <cstdint>

// Problem constants (fixed by the dataset)
constexpr int U_N  = 50000;
constexpr int I_N  = 100000;
constexpr int N_N  = 150000;   // U + I
constexpr int D    = 64;
constexpr int B_N  = 8192;
constexpr int HID  = 128;

// ---------------------------------------------------------------------------
// Scratch (device globals: allocation-free)
// ---------------------------------------------------------------------------
__device__ __align__(256) float g_ui_a[N_N * D];      // ping
__device__ __align__(256) float g_ui_b[N_N * D];      // pong
__device__ __align__(256) float g_hu[U_N * D];
__device__ __align__(256) float g_hi[I_N * D];
__device__ __align__(256) float g_zu[U_N * 2 * D];    // [U, 2, 64]
__device__ __align__(256) float g_zi[I_N * 2 * D];    // [I, 2, 64]
__device__ __align__(256) float g_dinv_ui[N_N];
__device__ __align__(256) float g_du[4 * U_N];        // u1_out, u1_in, u2_out, u2_in
__device__ __align__(256) float g_di[4 * I_N];        // i1_out, i1_in, i2_out, i2_in
__device__ __align__(256) float g_wsum[4];
__device__ __align__(256) float g_beta[2];

// ---------------------------------------------------------------------------
// Helpers
// ---------------------------------------------------------------------------
__device__ __forceinline__ float tanh_fast(float x) {
    float y;
    asm("tanh.approx.f32 %0, %1;" : "=f"(y) : "f"(x));
    return y;
}

__device__ __forceinline__ void red_add_v4(float* addr, float4 v) {
    asm volatile("red.global.add.v4.f32 [%0], {%1, %2, %3, %4};"
                 :: "l"(addr), "f"(v.x), "f"(v.y), "f"(v.z), "f"(v.w)
                 : "memory");
}

// ---------------------------------------------------------------------------
// Kernels
// ---------------------------------------------------------------------------
__global__ void zero4_k(float4* p, int n4) {
    int t = blockIdx.x * blockDim.x + threadIdx.x;
    if (t < n4) p[t] = make_float4(0.f, 0.f, 0.f, 0.f);
}

// copy user_feat/item_feat into ui concat + hu + hi
__global__ void init_k(const float4* __restrict__ uf, const float4* __restrict__ itf,
                       float4* __restrict__ ui, float4* __restrict__ hu,
                       float4* __restrict__ hi) {
    int t = blockIdx.x * blockDim.x + threadIdx.x;
    if (t >= N_N * 16) return;
    if (t < U_N * 16) {
        float4 v = uf[t];
        ui[t] = v; hu[t] = v;
    } else {
        float4 v = itf[t - U_N * 16];
        ui[t] = v; hi[t - U_N * 16] = v;
    }
}

__global__ void deg_count_k(const int* __restrict__ idx, int E, float* __restrict__ deg) {
    int t = blockIdx.x * blockDim.x + threadIdx.x;
    if (t < E) atomicAdd(&deg[idx[t]], 1.0f);
}

// gcn: dinv = deg>0 ? rsqrt(deg) : 0
__global__ void dinv_gcn_k(float* d, int n) {
    int t = blockIdx.x * blockDim.x + threadIdx.x;
    if (t < n) {
        float v = d[t];
        d[t] = (v > 0.f) ? rsqrtf(v) : 0.f;
    }
}

// graph_conv: dinv = rsqrt(max(deg,1))
__global__ void dinv_clamp_k(float* d, int n) {
    int t = blockIdx.x * blockDim.x + threadIdx.x;
    if (t < n) d[t] = rsqrtf(fmaxf(d[t], 1.0f));
}

// out[dst] += x[src] * wsrc[src]   (16 lanes per edge, float4 chunks)
__global__ void edge_scatter_k(const int* __restrict__ src, const int* __restrict__ dst,
                               int E, const float* __restrict__ x,
                               const float* __restrict__ wsrc,
                               float* __restrict__ out, int ostride, int ooff) {
    long long t = (long long)blockIdx.x * blockDim.x + threadIdx.x;
    int e = (int)(t >> 4);
    if (e >= E) return;
    int c = (int)(t & 15);
    int s = src[e];
    int d = dst[e];
    float w = __ldg(&wsrc[s]);
    float4 v = __ldg((const float4*)(x + (size_t)s * D) + c);
    v.x *= w; v.y *= w; v.z *= w; v.w *= w;
    red_add_v4(out + (size_t)d * ostride + ooff + c * 4, v);
}

// x[n,:] *= dinv[n]   (stride 64)
__global__ void row_scale_k(float* __restrict__ x, const float* __restrict__ dinv, int n) {
    int t = blockIdx.x * blockDim.x + threadIdx.x;
    if (t >= n * 16) return;
    float w = dinv[t >> 4];
    float4* p = (float4*)x + t;
    float4 v = *p;
    v.x *= w; v.y *= w; v.z *= w; v.w *= w;
    *p = v;
}

// z[n, m, :] *= dinv_in_m[n]   (z stride 128)
__global__ void z_scale_k(float* __restrict__ z, const float* __restrict__ dinv0,
                          const float* __restrict__ dinv1, int n) {
    int t = blockIdx.x * blockDim.x + threadIdx.x;
    if (t >= n * 32) return;
    int node = t >> 5;
    int m = (t >> 4) & 1;
    float w = m ? dinv1[node] : dinv0[node];
    float4* p = (float4*)z + t;   // t*4 = node*128 + m*64 + c*4
    float4 v = *p;
    v.x *= w; v.y *= w; v.z *= w; v.w *= w;
    *p = v;
}

// wsum[m] += sum_n ( tanh(z[n,m,:] @ W1 + b1) @ w2 )
__global__ void han_attn_k(const float* __restrict__ z, int n,
                           const float* __restrict__ W1, const float* __restrict__ b1,
                           const float* __restrict__ w2, float* __restrict__ wsum) {
    __shared__ float W1t[D * HID];   // transposed: [h][k]
    __shared__ float b1s[HID];
    __shared__ float w2s[HID];
    for (int i = threadIdx.x; i < D * HID; i += blockDim.x) {
        int k = i >> 7;        // i / 128
        int h = i & 127;       // i % 128
        W1t[h * D + k] = W1[i];
    }
    if (threadIdx.x < HID) {
        b1s[threadIdx.x] = b1[threadIdx.x];
        w2s[threadIdx.x] = w2[threadIdx.x];
    }
    __syncthreads();

    float acc0 = 0.f, acc1 = 0.f;
    int total = 2 * n;
    for (int p = blockIdx.x * blockDim.x + threadIdx.x; p < total;
         p += gridDim.x * blockDim.x) {
        const float4* zr = (const float4*)(z + (size_t)p * D);
        float4 zv[16];
        #pragma unroll
        for (int c = 0; c < 16; c++) zv[c] = zr[c];
        float s = 0.f;
        for (int h = 0; h < HID; h++) {
            const float4* wr = (const float4*)(W1t + h * D);
            float a0 = b1s[h], a1 = 0.f, a2 = 0.f, a3 = 0.f;
            #pragma unroll
            for (int c = 0; c < 16; c++) {
                float4 w = wr[c];
                a0 = fmaf(zv[c].x, w.x, a0);
                a1 = fmaf(zv[c].y, w.y, a1);
                a2 = fmaf(zv[c].z, w.z, a2);
                a3 = fmaf(zv[c].w, w.w, a3);
            }
            float a = (a0 + a1) + (a2 + a3);
            s = fmaf(tanh_fast(a), w2s[h], s);
        }
        if (p & 1) acc1 += s; else acc0 += s;
    }

    __shared__ float r0[256], r1[256];
    r0[threadIdx.x] = acc0;
    r1[threadIdx.x] = acc1;
    __syncthreads();
    for (int s = blockDim.x >> 1; s > 0; s >>= 1) {
        if (threadIdx.x < s) {
            r0[threadIdx.x] += r0[threadIdx.x + s];
            r1[threadIdx.x] += r1[threadIdx.x + s];
        }
        __syncthreads();
    }
    if (threadIdx.x == 0) {
        atomicAdd(&wsum[0], r0[0]);
        atomicAdd(&wsum[1], r1[0]);
    }
}

__global__ void beta_k(const float* __restrict__ wsum, float inv_n, float* __restrict__ beta) {
    float a = wsum[0] * inv_n;
    float b = wsum[1] * inv_n;
    float m = fmaxf(a, b);
    float e0 = expf(a - m), e1 = expf(b - m);
    float inv = 1.f / (e0 + e1);
    beta[0] = e0 * inv;
    beta[1] = e1 * inv;
}

// h[n,:] = beta0*z[n,0,:] + beta1*z[n,1,:]
__global__ void combine_k(const float* __restrict__ z, const float* __restrict__ beta,
                          float* __restrict__ h, int n) {
    int t = blockIdx.x * blockDim.x + threadIdx.x;
    if (t >= n * 16) return;
    int node = t >> 4;
    int c = t & 15;
    float b0 = beta[0], b1 = beta[1];
    float4 z0 = ((const float4*)z)[node * 32 + c];
    float4 z1 = ((const float4*)z)[node * 32 + 16 + c];
    float4 r;
    r.x = b0 * z0.x + b1 * z1.x;
    r.y = b0 * z0.y + b1 * z1.y;
    r.z = b0 * z0.z + b1 * z1.z;
    r.w = b0 * z0.w + b1 * z1.w;
    ((float4*)h)[t] = r;
}

__global__ void out_k(const float* __restrict__ hu, const float* __restrict__ hi,
                      const float* __restrict__ ui,
                      const int* __restrict__ uidx, const int* __restrict__ iidx,
                      const int* __restrict__ nidx, float* __restrict__ out) {
    int t = blockIdx.x * blockDim.x + threadIdx.x;
    if (t >= B_N * 16) return;
    int b = t >> 4;
    int c = t & 15;
    const float4* hu4 = (const float4*)hu;
    const float4* hi4 = (const float4*)hi;
    const float4* ui4 = (const float4*)ui;
    float4* o4 = (float4*)out;

    int u = uidx[b];
    float4 a = hu4[u * 16 + c];
    float4 g = ui4[u * 16 + c];
    float4 r;
    r.x = 0.5f * (a.x + g.x); r.y = 0.5f * (a.y + g.y);
    r.z = 0.5f * (a.z + g.z); r.w = 0.5f * (a.w + g.w);
    o4[t] = r;

    int it = iidx[b];
    a = hi4[it * 16 + c];
    g = ui4[(U_N + it) * 16 + c];
    r.x = 0.5f * (a.x + g.x); r.y = 0.5f * (a.y + g.y);
    r.z = 0.5f * (a.z + g.z); r.w = 0.5f * (a.w + g.w);
    o4[B_N * 16 + t] = r;

    int ni = nidx[b];
    int itn = iidx[ni];
    a = hi4[itn * 16 + c];
    g = ui4[(U_N + itn) * 16 + c];
    r.x = 0.5f * (a.x + g.x); r.y = 0.5f * (a.y + g.y);
    r.z = 0.5f * (a.z + g.z); r.w = 0.5f * (a.w + g.w);
    o4[2 * B_N * 16 + t] = r;
}

// ---------------------------------------------------------------------------
// Host
// ---------------------------------------------------------------------------
static inline int nblk(long long n) { return (int)((n + 255) / 256); }

extern "C" void kernel_launch(void* const* d_in, const int* in_sizes, int n_in,
                              void* d_out, int out_size) {
    const float* user_feat = (const float*)d_in[0];
    const float* item_feat = (const float*)d_in[1];
    const float* sa_u_W1   = (const float*)d_in[2];
    const float* sa_u_b1   = (const float*)d_in[3];
    const float* sa_u_w2   = (const float*)d_in[4];
    const float* sa_i_W1   = (const float*)d_in[5];
    const float* sa_i_b1   = (const float*)d_in[6];
    const float* sa_i_w2   = (const float*)d_in[7];
    const int*   ui_e      = (const int*)d_in[8];
    const int*   ue1       = (const int*)d_in[9];
    const int*   ue2       = (const int*)d_in[10];
    const int*   ie1       = (const int*)d_in[11];
    const int*   ie2       = (const int*)d_in[12];
    const int*   uidx      = (const int*)d_in[13];
    const int*   iidx      = (const int*)d_in[14];
    const int*   nidx      = (const int*)d_in[15];

    const int Eui = in_sizes[8]  / 2;   // 2,000,000 (row then col)
    const int Eu  = in_sizes[9]  / 2;   //   500,000 (src then dst)
    const int Ei  = in_sizes[11] / 2;   // 1,000,000

    float *ui_a, *ui_b, *hu, *hi, *zu, *zi, *dinv_ui, *du, *di, *wsum, *beta;
    cudaGetSymbolAddress((void**)&ui_a,    g_ui_a);
    cudaGetSymbolAddress((void**)&ui_b,    g_ui_b);
    cudaGetSymbolAddress((void**)&hu,      g_hu);
    cudaGetSymbolAddress((void**)&hi,      g_hi);
    cudaGetSymbolAddress((void**)&zu,      g_zu);
    cudaGetSymbolAddress((void**)&zi,      g_zi);
    cudaGetSymbolAddress((void**)&dinv_ui, g_dinv_ui);
    cudaGetSymbolAddress((void**)&du,      g_du);
    cudaGetSymbolAddress((void**)&di,      g_di);
    cudaGetSymbolAddress((void**)&wsum,    g_wsum);
    cudaGetSymbolAddress((void**)&beta,    g_beta);

    const int T = 256;

    // ---- init features ----
    init_k<<<nblk((long long)N_N * 16), T>>>((const float4*)user_feat,
                                             (const float4*)item_feat,
                                             (float4*)ui_a, (float4*)hu, (float4*)hi);

    // ---- degrees (once) ----
    zero4_k<<<nblk(N_N / 4), T>>>((float4*)dinv_ui, N_N / 4);
    zero4_k<<<nblk(4 * U_N / 4), T>>>((float4*)du, 4 * U_N / 4);
    zero4_k<<<nblk(4 * I_N / 4), T>>>((float4*)di, 4 * I_N / 4);

    deg_count_k<<<nblk(Eui), T>>>(ui_e, Eui, dinv_ui);              // row of symmetric adj
    deg_count_k<<<nblk(Eu),  T>>>(ue1,      Eu, du + 0 * U_N);      // u1 src -> dout
    deg_count_k<<<nblk(Eu),  T>>>(ue1 + Eu, Eu, du + 1 * U_N);      // u1 dst -> din
    deg_count_k<<<nblk(Eu),  T>>>(ue2,      Eu, du + 2 * U_N);      // u2 src
    deg_count_k<<<nblk(Eu),  T>>>(ue2 + Eu, Eu, du + 3 * U_N);      // u2 dst
    deg_count_k<<<nblk(Ei),  T>>>(ie1,      Ei, di + 0 * I_N);
    deg_count_k<<<nblk(Ei),  T>>>(ie1 + Ei, Ei, di + 1 * I_N);
    deg_count_k<<<nblk(Ei),  T>>>(ie2,      Ei, di + 2 * I_N);
    deg_count_k<<<nblk(Ei),  T>>>(ie2 + Ei, Ei, di + 3 * I_N);

    dinv_gcn_k<<<nblk(N_N), T>>>(dinv_ui, N_N);
    dinv_clamp_k<<<nblk(4 * U_N), T>>>(du, 4 * U_N);
    dinv_clamp_k<<<nblk(4 * I_N), T>>>(di, 4 * I_N);

    // ---- 2 propagation iterations ----
    const float* ui_in = ui_a;
    float* ui_out = ui_b;
    for (int iter = 0; iter < 2; ++iter) {
        // gcn_spmm: out[row] += x[col]*dinv[col]; out[row] *= dinv[row]
        zero4_k<<<nblk((long long)N_N * 16), T>>>((float4*)ui_out, N_N * 16);
        edge_scatter_k<<<nblk((long long)Eui * 16), T>>>(
            ui_e + Eui /*col=src*/, ui_e /*row=dst*/, Eui, ui_in, dinv_ui, ui_out, 64, 0);
        row_scale_k<<<nblk((long long)N_N * 16), T>>>(ui_out, dinv_ui, N_N);

        // user HAN layer
        zero4_k<<<nblk((long long)U_N * 32), T>>>((float4*)zu, U_N * 32);
        edge_scatter_k<<<nblk((long long)Eu * 16), T>>>(ue1, ue1 + Eu, Eu, hu, du + 0 * U_N, zu, 128, 0);
        edge_scatter_k<<<nblk((long long)Eu * 16), T>>>(ue2, ue2 + Eu, Eu, hu, du + 2 * U_N, zu, 128, 64);
        z_scale_k<<<nblk((long long)U_N * 32), T>>>(zu, du + 1 * U_N, du + 3 * U_N, U_N);
        zero4_k<<<1, T>>>((float4*)wsum, 1);
        han_attn_k<<<nblk((long long)2 * U_N), 256>>>(zu, U_N, sa_u_W1, sa_u_b1, sa_u_w2, wsum);
        beta_k<<<1, 1>>>(wsum, 1.0f / U_N, beta);
        combine_k<<<nblk((long long)U_N * 16), T>>>(zu, beta, hu, U_N);

        // item HAN layer
        zero4_k<<<nblk((long long)I_N * 32), T>>>((float4*)zi, I_N * 32);
        edge_scatter_k<<<nblk((long long)Ei * 16), T>>>(ie1, ie1 + Ei, Ei, hi, di + 0 * I_N, zi, 128, 0);
        edge_scatter_k<<<nblk((long long)Ei * 16), T>>>(ie2, ie2 + Ei, Ei, hi, di + 2 * I_N, zi, 128, 64);
        z_scale_k<<<nblk((long long)I_N * 32), T>>>(zi, di + 1 * I_N, di + 3 * I_N, I_N);
        zero4_k<<<1, T>>>((float4*)wsum, 1);
        han_attn_k<<<nblk((long long)2 * I_N), 256>>>(zi, I_N, sa_i_W1, sa_i_b1, sa_i_w2, wsum);
        beta_k<<<1, 1>>>(wsum, 1.0f / I_N, beta);
        combine_k<<<nblk((long long)I_N * 16), T>>>(zi, beta, hi, I_N);

        // swap ui ping-pong
        const float* tmp_in = ui_in;
        ui_in = ui_out;
        ui_out = (float*)tmp_in;
    }

    // ---- epilogue: blend + gathers ----
    out_k<<<nblk((long long)B_N * 16), T>>>(hu, hi, ui_in, uidx, iidx, nidx, (float*)d_out);
}

// round 2
// speedup vs baseline: 1.3366x; 1.3366x over previous
#include <cuda_runtime.h>
#include <cstdint>

// Problem constants (fixed by the dataset)
constexpr int U_N  = 50000;
constexpr int I_N  = 100000;
constexpr int N_N  = 150000;   // U + I
constexpr int D    = 64;
constexpr int B_N  = 8192;
constexpr int HID  = 128;

constexpr int NTOT  = N_N + 2 * U_N + 2 * I_N;   // 450000 CSR rows (5 graphs)
constexpr int NSCAN = NTOT + 1;                  // +1 for total sentinel
constexpr int E_TOT = 5000000;                   // 2M + 2*0.5M + 2*1M edges

// int scratch layout
constexpr int OFF_DEG  = 0;                      // NSCAN (padded)
constexpr int DEG_PAD  = 450008;
constexpr int OFF_CNT  = DEG_PAD;                // NTOT cursors (padded)
constexpr int CNT_PAD  = 450008;
constexpr int OFF_DOUT = OFF_CNT + CNT_PAD;      // 2U+2I out-degrees
constexpr int DOUT_LEN = 2 * U_N + 2 * I_N;      // 300000
constexpr int OFF_PART = OFF_DOUT + DOUT_LEN;    // scan partials
constexpr int INT_TOT  = OFF_PART + 256;         // 1200272 (div by 4)

// CSR row bases within the concatenated degree/scan vector
constexpr int RB_GCN = 0;
constexpr int RB_U1  = N_N;
constexpr int RB_U2  = N_N + U_N;
constexpr int RB_I1  = N_N + 2 * U_N;
constexpr int RB_I2  = N_N + 2 * U_N + I_N;

// ---------------------------------------------------------------------------
// Scratch (device globals: allocation-free)
// ---------------------------------------------------------------------------
__device__ __align__(256) float g_ui_a[N_N * D];
__device__ __align__(256) float g_ui_b[N_N * D];
__device__ __align__(256) float g_hu[U_N * D];
__device__ __align__(256) float g_hi[I_N * D];
__device__ __align__(256) float g_zu[U_N * 2 * D];
__device__ __align__(256) float g_zi[I_N * 2 * D];
__device__ __align__(256) float g_wdst[NTOT];        // gcn dinv | din_inv per metapath
__device__ __align__(256) float g_wsrc[DOUT_LEN];    // dout_inv per metapath
__device__ __align__(256) float g_wsum[4];
__device__ __align__(256) float g_beta[4];           // [0..1]=user, [2..3]=item
__device__ __align__(256) int   g_int[INT_TOT];
__device__ __align__(256) int   g_S[NSCAN + 8];      // global exclusive scan
__device__ __align__(256) int   g_csr[E_TOT];        // all 5 graphs' neighbor lists

// ---------------------------------------------------------------------------
// Helpers
// ---------------------------------------------------------------------------
__device__ __forceinline__ float tanh_fast(float x) {
    float y;
    asm("tanh.approx.f32 %0, %1;" : "=f"(y) : "f"(x));
    return y;
}
__device__ __forceinline__ unsigned long long ffma2(unsigned long long a,
                                                    unsigned long long b,
                                                    unsigned long long c) {
    unsigned long long d;
    asm("fma.rn.f32x2 %0, %1, %2, %3;" : "=l"(d) : "l"(a), "l"(b), "l"(c));
    return d;
}
__device__ __forceinline__ unsigned long long pack2(float lo, float hi) {
    unsigned long long r;
    asm("mov.b64 %0, {%1, %2};" : "=l"(r) : "f"(lo), "f"(hi));
    return r;
}
__device__ __forceinline__ float2 unpack2(unsigned long long v) {
    float2 r;
    asm("mov.b64 {%0, %1}, %2;" : "=f"(r.x), "=f"(r.y) : "l"(v));
    return r;
}

// ---------------------------------------------------------------------------
// Kernels
// ---------------------------------------------------------------------------
__global__ void zero_i4_k(int4* p, int n4) {
    int t = blockIdx.x * blockDim.x + threadIdx.x;
    if (t < n4) p[t] = make_int4(0, 0, 0, 0);
}

__global__ void init_k(const float4* __restrict__ uf, const float4* __restrict__ itf,
                       float4* __restrict__ ui, float4* __restrict__ hu,
                       float4* __restrict__ hi) {
    int t = blockIdx.x * blockDim.x + threadIdx.x;
    if (t >= N_N * 16) return;
    if (t < U_N * 16) {
        float4 v = uf[t];
        ui[t] = v; hu[t] = v;
    } else {
        float4 v = itf[t - U_N * 16];
        ui[t] = v; hi[t - U_N * 16] = v;
    }
}

__global__ void cnt_k(const int* __restrict__ idx, int E, int* __restrict__ deg) {
    int t = blockIdx.x * blockDim.x + threadIdx.x;
    if (t < E) atomicAdd(&deg[idx[t]], 1);
}

// --- 3-phase exclusive scan over NSCAN ints (chunk = 2048) ---
__global__ void scan1_k(const int* __restrict__ deg, int n,
                        int* __restrict__ S, int* __restrict__ part) {
    __shared__ int warpsum[8];
    int base = blockIdx.x * 2048 + threadIdx.x * 8;
    int v[8];
    int s = 0;
    #pragma unroll
    for (int i = 0; i < 8; i++) {
        int x = (base + i < n) ? deg[base + i] : 0;
        v[i] = s; s += x;
    }
    int lane = threadIdx.x & 31, w = threadIdx.x >> 5;
    int ts = s;
    #pragma unroll
    for (int o = 1; o < 32; o <<= 1) {
        int y = __shfl_up_sync(0xffffffffu, ts, o);
        if (lane >= o) ts += y;
    }
    if (lane == 31) warpsum[w] = ts;
    __syncthreads();
    if (w == 0 && lane < 8) {
        int x = warpsum[lane];
        #pragma unroll
        for (int o = 1; o < 8; o <<= 1) {
            int y = __shfl_up_sync(0xffu, x, o);
            if (lane >= o) x += y;
        }
        warpsum[lane] = x;
    }
    __syncthreads();
    int prefix = (w > 0 ? warpsum[w - 1] : 0) + (ts - s);
    #pragma unroll
    for (int i = 0; i < 8; i++)
        if (base + i < n) S[base + i] = prefix + v[i];
    if (threadIdx.x == 0) part[blockIdx.x] = warpsum[7];
}

__global__ void scan2_k(int* part, int np) {
    __shared__ int sh[256];
    int t = threadIdx.x;
    int x = (t < np) ? part[t] : 0;
    sh[t] = x;
    __syncthreads();
    for (int o = 1; o < 256; o <<= 1) {
        int y = (t >= o) ? sh[t - o] : 0;
        __syncthreads();
        sh[t] += y;
        __syncthreads();
    }
    if (t < np) part[t] = sh[t] - x;  // exclusive
}

__global__ void scan3_k(int* __restrict__ S, const int* __restrict__ part, int n) {
    int t = blockIdx.x * blockDim.x + threadIdx.x;
    if (t < n) S[t] += part[t >> 11];
}

__global__ void weights_k(const int* __restrict__ din, const int* __restrict__ dout,
                          float* __restrict__ wdst, float* __restrict__ wsrc) {
    int t = blockIdx.x * blockDim.x + threadIdx.x;
    if (t < NTOT) {
        float d = (float)din[t];
        wdst[t] = (t < N_N) ? ((d > 0.f) ? rsqrtf(d) : 0.f)
                            : rsqrtf(fmaxf(d, 1.f));
    }
    if (t < DOUT_LEN) wsrc[t] = rsqrtf(fmaxf((float)dout[t], 1.f));
}

__global__ void fill_k(const int* __restrict__ src, const int* __restrict__ dst, int E,
                       const int* __restrict__ S, int row_base,
                       int* __restrict__ cnt, int* __restrict__ csr) {
    int e = blockIdx.x * blockDim.x + threadIdx.x;
    if (e >= E) return;
    int d = dst[e];
    int p = atomicAdd(&cnt[row_base + d], 1);
    csr[S[row_base + d] + p] = src[e];
}

// warp-per-row CSR pull SpMM: out[r] = wdst[r] * sum_c wsrc[c]*in[c]
__global__ void pull_k(const int* __restrict__ S, const int* __restrict__ csr,
                       const float* __restrict__ wsrc, const float* __restrict__ wdst,
                       const float* __restrict__ in, float* __restrict__ out,
                       int nrows, int ostride, int ooff) {
    int r = (blockIdx.x * blockDim.x + threadIdx.x) >> 5;
    if (r >= nrows) return;
    int lane = threadIdx.x & 31;
    int s = S[r], e = S[r + 1];
    float2 acc = make_float2(0.f, 0.f);
    int j = s;
    for (; j + 4 <= e; j += 4) {
        int c0 = csr[j], c1 = csr[j + 1], c2 = csr[j + 2], c3 = csr[j + 3];
        float w0 = wsrc[c0], w1 = wsrc[c1], w2 = wsrc[c2], w3 = wsrc[c3];
        float2 v0 = *(const float2*)(in + (size_t)c0 * D + lane * 2);
        float2 v1 = *(const float2*)(in + (size_t)c1 * D + lane * 2);
        float2 v2 = *(const float2*)(in + (size_t)c2 * D + lane * 2);
        float2 v3 = *(const float2*)(in + (size_t)c3 * D + lane * 2);
        acc.x = fmaf(w0, v0.x, acc.x); acc.y = fmaf(w0, v0.y, acc.y);
        acc.x = fmaf(w1, v1.x, acc.x); acc.y = fmaf(w1, v1.y, acc.y);
        acc.x = fmaf(w2, v2.x, acc.x); acc.y = fmaf(w2, v2.y, acc.y);
        acc.x = fmaf(w3, v3.x, acc.x); acc.y = fmaf(w3, v3.y, acc.y);
    }
    for (; j < e; j++) {
        int c = csr[j];
        float w = wsrc[c];
        float2 v = *(const float2*)(in + (size_t)c * D + lane * 2);
        acc.x = fmaf(w, v.x, acc.x); acc.y = fmaf(w, v.y, acc.y);
    }
    float wd = wdst[r];
    float2 o = make_float2(acc.x * wd, acc.y * wd);
    *(float2*)(out + (size_t)r * ostride + ooff + lane * 2) = o;
}

// wsum[m] += sum_n ( tanh(z[n,m,:] @ W1 + b1) @ w2 )  — packed f32x2 FMA
__global__ void han_attn_k(const float* __restrict__ z, int n,
                           const float* __restrict__ W1, const float* __restrict__ b1,
                           const float* __restrict__ w2, float* __restrict__ wsum) {
    __shared__ unsigned long long W1p[HID * 32];  // [h][kpair]
    __shared__ float b1s[HID];
    __shared__ float w2s[HID];
    for (int i = threadIdx.x; i < HID * 32; i += blockDim.x) {
        int h = i >> 5, kp = i & 31;
        W1p[i] = pack2(W1[(2 * kp) * HID + h], W1[(2 * kp + 1) * HID + h]);
    }
    if (threadIdx.x < HID) {
        b1s[threadIdx.x] = b1[threadIdx.x];
        w2s[threadIdx.x] = w2[threadIdx.x];
    }
    __syncthreads();

    float acc0 = 0.f, acc1 = 0.f;
    int total = 2 * n;
    for (int p = blockIdx.x * blockDim.x + threadIdx.x; p < total;
         p += gridDim.x * blockDim.x) {
        const ulonglong2* zr = (const ulonglong2*)(z + (size_t)p * D);
        unsigned long long zv[32];
        #pragma unroll
        for (int c = 0; c < 16; c++) {
            ulonglong2 t = zr[c];
            zv[2 * c] = t.x; zv[2 * c + 1] = t.y;
        }
        float s = 0.f;
        for (int h = 0; h < HID; h++) {
            const unsigned long long* wr = &W1p[h << 5];
            unsigned long long a = 0ull, b = 0ull;
            #pragma unroll
            for (int kp = 0; kp < 32; kp += 2) {
                a = ffma2(zv[kp],     wr[kp],     a);
                b = ffma2(zv[kp + 1], wr[kp + 1], b);
            }
            float2 fa = unpack2(a), fb = unpack2(b);
            float v = (fa.x + fa.y) + (fb.x + fb.y) + b1s[h];
            s = fmaf(tanh_fast(v), w2s[h], s);
        }
        if (p & 1) acc1 += s; else acc0 += s;
    }

    __shared__ float r0[256], r1[256];
    r0[threadIdx.x] = acc0;
    r1[threadIdx.x] = acc1;
    __syncthreads();
    for (int s = blockDim.x >> 1; s > 0; s >>= 1) {
        if (threadIdx.x < s) {
            r0[threadIdx.x] += r0[threadIdx.x + s];
            r1[threadIdx.x] += r1[threadIdx.x + s];
        }
        __syncthreads();
    }
    if (threadIdx.x == 0) {
        atomicAdd(&wsum[0], r0[0]);
        atomicAdd(&wsum[1], r1[0]);
    }
}

__global__ void beta_k(const float* __restrict__ wsum, float inv_n, float* __restrict__ beta) {
    float a = wsum[0] * inv_n;
    float b = wsum[1] * inv_n;
    float m = fmaxf(a, b);
    float e0 = expf(a - m), e1 = expf(b - m);
    float inv = 1.f / (e0 + e1);
    beta[0] = e0 * inv;
    beta[1] = e1 * inv;
}

__global__ void zero_wsum_k(float* w) {
    if (threadIdx.x < 4) w[threadIdx.x] = 0.f;
}

// h[n,:] = beta0*z[n,0,:] + beta1*z[n,1,:]   (iteration 1 only)
__global__ void combine_k(const float* __restrict__ z, const float* __restrict__ beta,
                          float* __restrict__ h, int n) {
    int t = blockIdx.x * blockDim.x + threadIdx.x;
    if (t >= n * 16) return;
    int node = t >> 4;
    int c = t & 15;
    float b0 = beta[0], b1 = beta[1];
    float4 z0 = ((const float4*)z)[node * 32 + c];
    float4 z1 = ((const float4*)z)[node * 32 + 16 + c];
    float4 r;
    r.x = fmaf(b0, z0.x, b1 * z1.x);
    r.y = fmaf(b0, z0.y, b1 * z1.y);
    r.z = fmaf(b0, z0.z, b1 * z1.z);
    r.w = fmaf(b0, z0.w, b1 * z1.w);
    ((float4*)h)[t] = r;
}

// epilogue: iter-2 combine fused into the batched gathers
__global__ void out_k(const float* __restrict__ zu, const float* __restrict__ zi,
                      const float* __restrict__ ui, const float* __restrict__ beta,
                      const int* __restrict__ uidx, const int* __restrict__ iidx,
                      const int* __restrict__ nidx, float* __restrict__ out) {
    int t = blockIdx.x * blockDim.x + threadIdx.x;
    if (t >= B_N * 16) return;
    int b = t >> 4;
    int c = t & 15;
    const float4* zu4 = (const float4*)zu;
    const float4* zi4 = (const float4*)zi;
    const float4* ui4 = (const float4*)ui;
    float4* o4 = (float4*)out;
    float bU0 = beta[0], bU1 = beta[1], bI0 = beta[2], bI1 = beta[3];

    {
        int u = uidx[b];
        float4 z0 = zu4[u * 32 + c];
        float4 z1 = zu4[u * 32 + 16 + c];
        float4 g = ui4[u * 16 + c];
        float4 r;
        r.x = 0.5f * (fmaf(bU0, z0.x, bU1 * z1.x) + g.x);
        r.y = 0.5f * (fmaf(bU0, z0.y, bU1 * z1.y) + g.y);
        r.z = 0.5f * (fmaf(bU0, z0.z, bU1 * z1.z) + g.z);
        r.w = 0.5f * (fmaf(bU0, z0.w, bU1 * z1.w) + g.w);
        o4[t] = r;
    }
    {
        int it = iidx[b];
        float4 z0 = zi4[it * 32 + c];
        float4 z1 = zi4[it * 32 + 16 + c];
        float4 g = ui4[(U_N + it) * 16 + c];
        float4 r;
        r.x = 0.5f * (fmaf(bI0, z0.x, bI1 * z1.x) + g.x);
        r.y = 0.5f * (fmaf(bI0, z0.y, bI1 * z1.y) + g.y);
        r.z = 0.5f * (fmaf(bI0, z0.z, bI1 * z1.z) + g.z);
        r.w = 0.5f * (fmaf(bI0, z0.w, bI1 * z1.w) + g.w);
        o4[B_N * 16 + t] = r;
    }
    {
        int itn = iidx[nidx[b]];
        float4 z0 = zi4[itn * 32 + c];
        float4 z1 = zi4[itn * 32 + 16 + c];
        float4 g = ui4[(U_N + itn) * 16 + c];
        float4 r;
        r.x = 0.5f * (fmaf(bI0, z0.x, bI1 * z1.x) + g.x);
        r.y = 0.5f * (fmaf(bI0, z0.y, bI1 * z1.y) + g.y);
        r.z = 0.5f * (fmaf(bI0, z0.z, bI1 * z1.z) + g.z);
        r.w = 0.5f * (fmaf(bI0, z0.w, bI1 * z1.w) + g.w);
        o4[2 * B_N * 16 + t] = r;
    }
}

// ---------------------------------------------------------------------------
// Host
// ---------------------------------------------------------------------------
static inline int nblk(long long n) { return (int)((n + 255) / 256); }

extern "C" void kernel_launch(void* const* d_in, const int* in_sizes, int n_in,
                              void* d_out, int out_size) {
    const float* user_feat = (const float*)d_in[0];
    const float* item_feat = (const float*)d_in[1];
    const float* sa_u_W1   = (const float*)d_in[2];
    const float* sa_u_b1   = (const float*)d_in[3];
    const float* sa_u_w2   = (const float*)d_in[4];
    const float* sa_i_W1   = (const float*)d_in[5];
    const float* sa_i_b1   = (const float*)d_in[6];
    const float* sa_i_w2   = (const float*)d_in[7];
    const int*   ui_e      = (const int*)d_in[8];
    const int*   ue1       = (const int*)d_in[9];
    const int*   ue2       = (const int*)d_in[10];
    const int*   ie1       = (const int*)d_in[11];
    const int*   ie2       = (const int*)d_in[12];
    const int*   uidx      = (const int*)d_in[13];
    const int*   iidx      = (const int*)d_in[14];
    const int*   nidx      = (const int*)d_in[15];

    const int Eui = in_sizes[8]  / 2;   // 2,000,000 (row then col)
    const int Eu  = in_sizes[9]  / 2;   //   500,000 (src then dst)
    const int Ei  = in_sizes[11] / 2;   // 1,000,000

    float *ui_a, *ui_b, *hu, *hi, *zu, *zi, *wdst, *wsrc, *wsum, *beta;
    int *ibuf, *S, *csr;
    cudaGetSymbolAddress((void**)&ui_a, g_ui_a);
    cudaGetSymbolAddress((void**)&ui_b, g_ui_b);
    cudaGetSymbolAddress((void**)&hu,   g_hu);
    cudaGetSymbolAddress((void**)&hi,   g_hi);
    cudaGetSymbolAddress((void**)&zu,   g_zu);
    cudaGetSymbolAddress((void**)&zi,   g_zi);
    cudaGetSymbolAddress((void**)&wdst, g_wdst);
    cudaGetSymbolAddress((void**)&wsrc, g_wsrc);
    cudaGetSymbolAddress((void**)&wsum, g_wsum);
    cudaGetSymbolAddress((void**)&beta, g_beta);
    cudaGetSymbolAddress((void**)&ibuf, g_int);
    cudaGetSymbolAddress((void**)&S,    g_S);
    cudaGetSymbolAddress((void**)&csr,  g_csr);

    int* deg  = ibuf + OFF_DEG;
    int* cnt  = ibuf + OFF_CNT;
    int* dout = ibuf + OFF_DOUT;
    int* part = ibuf + OFF_PART;

    const int T = 256;

    // ---- zero int scratch (degrees, cursors, out-degrees, partials) ----
    zero_i4_k<<<nblk(INT_TOT / 4), T>>>((int4*)ibuf, INT_TOT / 4);

    // ---- init features ----
    init_k<<<nblk((long long)N_N * 16), T>>>((const float4*)user_feat,
                                             (const float4*)item_feat,
                                             (float4*)ui_a, (float4*)hu, (float4*)hi);

    // ---- degree counts (din into deg-concat, dout separately) ----
    cnt_k<<<nblk(Eui), T>>>(ui_e,       Eui, deg + RB_GCN);  // gcn: bucket by row
    cnt_k<<<nblk(Eu),  T>>>(ue1 + Eu,   Eu,  deg + RB_U1);   // u1 din
    cnt_k<<<nblk(Eu),  T>>>(ue2 + Eu,   Eu,  deg + RB_U2);   // u2 din
    cnt_k<<<nblk(Ei),  T>>>(ie1 + Ei,   Ei,  deg + RB_I1);   // i1 din
    cnt_k<<<nblk(Ei),  T>>>(ie2 + Ei,   Ei,  deg + RB_I2);   // i2 din
    cnt_k<<<nblk(Eu),  T>>>(ue1,        Eu,  dout + 0);              // u1 dout
    cnt_k<<<nblk(Eu),  T>>>(ue2,        Eu,  dout + U_N);            // u2 dout
    cnt_k<<<nblk(Ei),  T>>>(ie1,        Ei,  dout + 2 * U_N);        // i1 dout
    cnt_k<<<nblk(Ei),  T>>>(ie2,        Ei,  dout + 2 * U_N + I_N);  // i2 dout

    // ---- global exclusive scan -> CSR row offsets (one scan, 5 graphs) ----
    const int nchunks = (NSCAN + 2047) / 2048;  // 220 <= 256
    scan1_k<<<nchunks, T>>>(deg, NSCAN, S, part);
    scan2_k<<<1, 256>>>(part, nchunks);
    scan3_k<<<nblk(NSCAN), T>>>(S, part, NSCAN);

    // ---- normalization weights ----
    weights_k<<<nblk(NTOT), T>>>(deg, dout, wdst, wsrc);

    // ---- CSR fill (atomic cursors) ----
    fill_k<<<nblk(Eui), T>>>(ui_e + Eui, ui_e,     Eui, S, RB_GCN, cnt, csr);
    fill_k<<<nblk(Eu),  T>>>(ue1,        ue1 + Eu, Eu,  S, RB_U1,  cnt, csr);
    fill_k<<<nblk(Eu),  T>>>(ue2,        ue2 + Eu, Eu,  S, RB_U2,  cnt, csr);
    fill_k<<<nblk(Ei),  T>>>(ie1,        ie1 + Ei, Ei,  S, RB_I1,  cnt, csr);
    fill_k<<<nblk(Ei),  T>>>(ie2,        ie2 + Ei, Ei,  S, RB_I2,  cnt, csr);

    // ---- 2 propagation iterations ----
    const float* ui_in = ui_a;
    float* ui_out = ui_b;
    for (int iter = 0; iter < 2; ++iter) {
        // gcn pull: fully scaled output
        pull_k<<<nblk((long long)N_N * 32), T>>>(S + RB_GCN, csr, wdst + RB_GCN,
                                                 wdst + RB_GCN, ui_in, ui_out,
                                                 N_N, 64, 0);
        // HAN pulls -> fully scaled z
        pull_k<<<nblk((long long)U_N * 32), T>>>(S + RB_U1, csr, wsrc + 0,
                                                 wdst + RB_U1, hu, zu, U_N, 128, 0);
        pull_k<<<nblk((long long)U_N * 32), T>>>(S + RB_U2, csr, wsrc + U_N,
                                                 wdst + RB_U2, hu, zu, U_N, 128, 64);
        pull_k<<<nblk((long long)I_N * 32), T>>>(S + RB_I1, csr, wsrc + 2 * U_N,
                                                 wdst + RB_I1, hi, zi, I_N, 128, 0);
        pull_k<<<nblk((long long)I_N * 32), T>>>(S + RB_I2, csr, wsrc + 2 * U_N + I_N,
                                                 wdst + RB_I2, hi, zi, I_N, 128, 64);

        zero_wsum_k<<<1, 32>>>(wsum);
        han_attn_k<<<nblk((long long)2 * U_N), 256>>>(zu, U_N, sa_u_W1, sa_u_b1,
                                                      sa_u_w2, wsum + 0);
        beta_k<<<1, 1>>>(wsum + 0, 1.0f / U_N, beta + 0);
        han_attn_k<<<nblk((long long)2 * I_N), 256>>>(zi, I_N, sa_i_W1, sa_i_b1,
                                                      sa_i_w2, wsum + 2);
        beta_k<<<1, 1>>>(wsum + 2, 1.0f / I_N, beta + 2);

        if (iter == 0) {
            combine_k<<<nblk((long long)U_N * 16), T>>>(zu, beta + 0, hu, U_N);
            combine_k<<<nblk((long long)I_N * 16), T>>>(zi, beta + 2, hi, I_N);
        }

        const float* tmp = ui_in;
        ui_in = ui_out;
        ui_out = (float*)tmp;
    }

    // ---- epilogue: fused iter-2 combine + blend + batched gathers ----
    out_k<<<nblk((long long)B_N * 16), T>>>(zu, zi, ui_in, beta,
                                            uidx, iidx, nidx, (float*)d_out);
}

// round 3
// speedup vs baseline: 2.1687x; 1.6225x over previous
#include <cuda_runtime.h>
#include <cuda_bf16.h>
#include <cstdint>

// Problem constants (fixed by the dataset)
constexpr int U_N  = 50000;
constexpr int I_N  = 100000;
constexpr int N_N  = 150000;   // U + I
constexpr int D    = 64;
constexpr int B_N  = 8192;
constexpr int HID  = 128;

constexpr int NTOT  = N_N + 2 * U_N + 2 * I_N;   // 450000 CSR rows (5 graphs)
constexpr int NSCAN = NTOT + 1;                  // +1 for total sentinel
constexpr int E_TOT = 5000000;                   // 2M + 2*0.5M + 2*1M edges

// int scratch layout
constexpr int OFF_DEG  = 0;
constexpr int DEG_PAD  = 450008;
constexpr int OFF_CNT  = DEG_PAD;
constexpr int CNT_PAD  = 450008;
constexpr int OFF_DOUT = OFF_CNT + CNT_PAD;
constexpr int DOUT_LEN = 2 * U_N + 2 * I_N;      // 300000
constexpr int OFF_PART = OFF_DOUT + DOUT_LEN;
constexpr int INT_TOT  = OFF_PART + 256;

// CSR row bases within the concatenated degree/scan vector
constexpr int RB_GCN = 0;
constexpr int RB_U1  = N_N;
constexpr int RB_U2  = N_N + U_N;
constexpr int RB_I1  = N_N + 2 * U_N;
constexpr int RB_I2  = N_N + 2 * U_N + I_N;

// ---------------------------------------------------------------------------
// Scratch (device globals: allocation-free)
// ---------------------------------------------------------------------------
__device__ __align__(256) float g_ui_a[N_N * D];
__device__ __align__(256) float g_ui_b[N_N * D];
__device__ __align__(256) float g_hu[U_N * D];
__device__ __align__(256) float g_hi[I_N * D];
__device__ __align__(256) float g_zu[U_N * 2 * D];
__device__ __align__(256) float g_zi[I_N * 2 * D];
__device__ __align__(256) float g_wdst[NTOT];
__device__ __align__(256) float g_wsrc[DOUT_LEN];
__device__ __align__(256) float g_wsum[4];
__device__ __align__(256) float g_beta[4];
__device__ __align__(256) int   g_int[INT_TOT];
__device__ __align__(256) int   g_S[NSCAN + 8];
__device__ __align__(256) int   g_csr[E_TOT];

// ---------------------------------------------------------------------------
// Helpers
// ---------------------------------------------------------------------------
__device__ __forceinline__ float tanh_fast(float x) {
    float y;
    asm("tanh.approx.f32 %0, %1;" : "=f"(y) : "f"(x));
    return y;
}
// pack two fp32 into bf16x2: lo = a, hi = b
__device__ __forceinline__ uint32_t pack_bf16(float lo, float hi) {
    uint32_t r;
    asm("cvt.rn.bf16x2.f32 %0, %1, %2;" : "=r"(r) : "f"(hi), "f"(lo));
    return r;
}
__device__ __forceinline__ void mma16816(float c[4], const uint32_t a[4],
                                         uint32_t b0, uint32_t b1) {
    asm volatile(
        "mma.sync.aligned.m16n8k16.row.col.f32.bf16.bf16.f32 "
        "{%0,%1,%2,%3}, {%4,%5,%6,%7}, {%8,%9}, {%0,%1,%2,%3};"
        : "+f"(c[0]), "+f"(c[1]), "+f"(c[2]), "+f"(c[3])
        : "r"(a[0]), "r"(a[1]), "r"(a[2]), "r"(a[3]), "r"(b0), "r"(b1));
}

// ---------------------------------------------------------------------------
// Kernels
// ---------------------------------------------------------------------------
__global__ void zero_i4_k(int4* p, int n4) {
    int t = blockIdx.x * blockDim.x + threadIdx.x;
    if (t < n4) p[t] = make_int4(0, 0, 0, 0);
}

__global__ void init_k(const float4* __restrict__ uf, const float4* __restrict__ itf,
                       float4* __restrict__ ui, float4* __restrict__ hu,
                       float4* __restrict__ hi) {
    int t = blockIdx.x * blockDim.x + threadIdx.x;
    if (t >= N_N * 16) return;
    if (t < U_N * 16) {
        float4 v = uf[t];
        ui[t] = v; hu[t] = v;
    } else {
        float4 v = itf[t - U_N * 16];
        ui[t] = v; hi[t - U_N * 16] = v;
    }
}

__global__ void cnt_k(const int* __restrict__ idx, int E, int* __restrict__ deg) {
    int t = blockIdx.x * blockDim.x + threadIdx.x;
    if (t < E) atomicAdd(&deg[idx[t]], 1);
}

// --- 3-phase exclusive scan over NSCAN ints (chunk = 2048) ---
__global__ void scan1_k(const int* __restrict__ deg, int n,
                        int* __restrict__ S, int* __restrict__ part) {
    __shared__ int warpsum[8];
    int base = blockIdx.x * 2048 + threadIdx.x * 8;
    int v[8];
    int s = 0;
    #pragma unroll
    for (int i = 0; i < 8; i++) {
        int x = (base + i < n) ? deg[base + i] : 0;
        v[i] = s; s += x;
    }
    int lane = threadIdx.x & 31, w = threadIdx.x >> 5;
    int ts = s;
    #pragma unroll
    for (int o = 1; o < 32; o <<= 1) {
        int y = __shfl_up_sync(0xffffffffu, ts, o);
        if (lane >= o) ts += y;
    }
    if (lane == 31) warpsum[w] = ts;
    __syncthreads();
    if (w == 0 && lane < 8) {
        int x = warpsum[lane];
        #pragma unroll
        for (int o = 1; o < 8; o <<= 1) {
            int y = __shfl_up_sync(0xffu, x, o);
            if (lane >= o) x += y;
        }
        warpsum[lane] = x;
    }
    __syncthreads();
    int prefix = (w > 0 ? warpsum[w - 1] : 0) + (ts - s);
    #pragma unroll
    for (int i = 0; i < 8; i++)
        if (base + i < n) S[base + i] = prefix + v[i];
    if (threadIdx.x == 0) part[blockIdx.x] = warpsum[7];
}

__global__ void scan2_k(int* part, int np) {
    __shared__ int sh[256];
    int t = threadIdx.x;
    int x = (t < np) ? part[t] : 0;
    sh[t] = x;
    __syncthreads();
    for (int o = 1; o < 256; o <<= 1) {
        int y = (t >= o) ? sh[t - o] : 0;
        __syncthreads();
        sh[t] += y;
        __syncthreads();
    }
    if (t < np) part[t] = sh[t] - x;  // exclusive
}

__global__ void scan3_k(int* __restrict__ S, const int* __restrict__ part, int n) {
    int t = blockIdx.x * blockDim.x + threadIdx.x;
    if (t < n) S[t] += part[t >> 11];
}

__global__ void weights_k(const int* __restrict__ din, const int* __restrict__ dout,
                          float* __restrict__ wdst, float* __restrict__ wsrc) {
    int t = blockIdx.x * blockDim.x + threadIdx.x;
    if (t < NTOT) {
        float d = (float)din[t];
        wdst[t] = (t < N_N) ? ((d > 0.f) ? rsqrtf(d) : 0.f)
                            : rsqrtf(fmaxf(d, 1.f));
    }
    if (t < DOUT_LEN) wsrc[t] = rsqrtf(fmaxf((float)dout[t], 1.f));
}

__global__ void fill_k(const int* __restrict__ src, const int* __restrict__ dst, int E,
                       const int* __restrict__ S, int row_base,
                       int* __restrict__ cnt, int* __restrict__ csr) {
    int e = blockIdx.x * blockDim.x + threadIdx.x;
    if (e >= E) return;
    int d = dst[e];
    int p = atomicAdd(&cnt[row_base + d], 1);
    csr[S[row_base + d] + p] = src[e];
}

// warp-per-row CSR pull SpMM: out[r] = wdst[r] * sum_c wsrc[c]*in[c]
__global__ void pull_k(const int* __restrict__ S, const int* __restrict__ csr,
                       const float* __restrict__ wsrc, const float* __restrict__ wdst,
                       const float* __restrict__ in, float* __restrict__ out,
                       int nrows, int ostride, int ooff) {
    int r = (blockIdx.x * blockDim.x + threadIdx.x) >> 5;
    if (r >= nrows) return;
    int lane = threadIdx.x & 31;
    int s = S[r], e = S[r + 1];
    float2 acc = make_float2(0.f, 0.f);
    int j = s;
    for (; j + 4 <= e; j += 4) {
        int c0 = csr[j], c1 = csr[j + 1], c2 = csr[j + 2], c3 = csr[j + 3];
        float w0 = wsrc[c0], w1 = wsrc[c1], w2 = wsrc[c2], w3 = wsrc[c3];
        float2 v0 = *(const float2*)(in + (size_t)c0 * D + lane * 2);
        float2 v1 = *(const float2*)(in + (size_t)c1 * D + lane * 2);
        float2 v2 = *(const float2*)(in + (size_t)c2 * D + lane * 2);
        float2 v3 = *(const float2*)(in + (size_t)c3 * D + lane * 2);
        acc.x = fmaf(w0, v0.x, acc.x); acc.y = fmaf(w0, v0.y, acc.y);
        acc.x = fmaf(w1, v1.x, acc.x); acc.y = fmaf(w1, v1.y, acc.y);
        acc.x = fmaf(w2, v2.x, acc.x); acc.y = fmaf(w2, v2.y, acc.y);
        acc.x = fmaf(w3, v3.x, acc.x); acc.y = fmaf(w3, v3.y, acc.y);
    }
    for (; j < e; j++) {
        int c = csr[j];
        float w = wsrc[c];
        float2 v = *(const float2*)(in + (size_t)c * D + lane * 2);
        acc.x = fmaf(w, v.x, acc.x); acc.y = fmaf(w, v.y, acc.y);
    }
    float wd = wdst[r];
    float2 o = make_float2(acc.x * wd, acc.y * wd);
    *(float2*)(out + (size_t)r * ostride + ooff + lane * 2) = o;
}

// ---------------------------------------------------------------------------
// HAN attention via bf16 tensor-core GEMM.
// wsum[m] += sum_n ( tanh(z[n,m,:] @ W1 + b1) @ w2 )
// Rows of z (interleaved m=0/1) processed 16 at a time per warp via
// mma.sync.m16n8k16. W1 (bf16, transposed, stride 72 for bank-conflict-free
// quad loads) lives in shared.
// ---------------------------------------------------------------------------
constexpr int WT_STRIDE = 72;

__global__ void han_attn_k(const float* __restrict__ z, int n,
                           const float* __restrict__ W1, const float* __restrict__ b1,
                           const float* __restrict__ w2, float* __restrict__ wsum) {
    __shared__ __align__(16) __nv_bfloat16 Wt[HID * WT_STRIDE];  // [h][k]
    __shared__ float b1s[HID];
    __shared__ float w2s[HID];
    __shared__ float r0s[256], r1s[256];

    for (int i = threadIdx.x; i < D * HID; i += blockDim.x) {
        int k = i >> 7, h = i & 127;
        Wt[h * WT_STRIDE + k] = __float2bfloat16(W1[i]);
    }
    if (threadIdx.x < HID) {
        b1s[threadIdx.x] = b1[threadIdx.x];
        w2s[threadIdx.x] = w2[threadIdx.x];
    }
    __syncthreads();

    int warp = threadIdx.x >> 5;
    int lane = threadIdx.x & 31;
    int g = lane >> 2;       // groupID (row within tile / n within 8-tile)
    int tig = lane & 3;      // thread in group (col pair)
    int ntiles = (2 * n) >> 4;   // rows divisible by 16 for these sizes

    float acc0 = 0.f, acc1 = 0.f;

    for (int tile = blockIdx.x * 8 + warp; tile < ntiles; tile += gridDim.x * 8) {
        const float* zb = z + (size_t)tile * 16 * D;
        // Load A fragments: 16 rows x 64 k, bf16
        uint32_t A[4][4];
        #pragma unroll
        for (int kt = 0; kt < 4; kt++) {
            int k0 = kt * 16 + tig * 2;
            float2 v;
            v = *(const float2*)(zb + g * D + k0);            A[kt][0] = pack_bf16(v.x, v.y);
            v = *(const float2*)(zb + (g + 8) * D + k0);      A[kt][1] = pack_bf16(v.x, v.y);
            v = *(const float2*)(zb + g * D + k0 + 8);        A[kt][2] = pack_bf16(v.x, v.y);
            v = *(const float2*)(zb + (g + 8) * D + k0 + 8);  A[kt][3] = pack_bf16(v.x, v.y);
        }
        float s0 = 0.f, s1 = 0.f;   // partial row scores (rows g and g+8)
        #pragma unroll
        for (int nt = 0; nt < 16; nt++) {
            float c[4] = {0.f, 0.f, 0.f, 0.f};
            const __nv_bfloat16* wrow = Wt + (nt * 8 + g) * WT_STRIDE;
            #pragma unroll
            for (int kt = 0; kt < 4; kt++) {
                uint32_t b0 = *(const uint32_t*)(wrow + kt * 16 + tig * 2);
                uint32_t b1v = *(const uint32_t*)(wrow + kt * 16 + tig * 2 + 8);
                mma16816(c, A[kt], b0, b1v);
            }
            int col0 = nt * 8 + tig * 2;
            float bb0 = b1s[col0], bb1 = b1s[col0 + 1];
            float ww0 = w2s[col0], ww1 = w2s[col0 + 1];
            s0 = fmaf(tanh_fast(c[0] + bb0), ww0, s0);
            s0 = fmaf(tanh_fast(c[1] + bb1), ww1, s0);
            s1 = fmaf(tanh_fast(c[2] + bb0), ww0, s1);
            s1 = fmaf(tanh_fast(c[3] + bb1), ww1, s1);
        }
        // reduce across the 4 lanes of each group (cols)
        s0 += __shfl_xor_sync(0xffffffffu, s0, 1);
        s0 += __shfl_xor_sync(0xffffffffu, s0, 2);
        s1 += __shfl_xor_sync(0xffffffffu, s1, 1);
        s1 += __shfl_xor_sync(0xffffffffu, s1, 2);
        if (tig == 0) {
            // rows g and g+8 share parity (g & 1) = metapath index
            float v = s0 + s1;
            if (g & 1) acc1 += v; else acc0 += v;
        }
    }

    r0s[threadIdx.x] = acc0;
    r1s[threadIdx.x] = acc1;
    __syncthreads();
    for (int s = blockDim.x >> 1; s > 0; s >>= 1) {
        if (threadIdx.x < s) {
            r0s[threadIdx.x] += r0s[threadIdx.x + s];
            r1s[threadIdx.x] += r1s[threadIdx.x + s];
        }
        __syncthreads();
    }
    if (threadIdx.x == 0) {
        atomicAdd(&wsum[0], r0s[0]);
        atomicAdd(&wsum[1], r1s[0]);
    }
}

__global__ void beta_k(const float* __restrict__ wsum, float inv_n, float* __restrict__ beta) {
    float a = wsum[0] * inv_n;
    float b = wsum[1] * inv_n;
    float m = fmaxf(a, b);
    float e0 = expf(a - m), e1 = expf(b - m);
    float inv = 1.f / (e0 + e1);
    beta[0] = e0 * inv;
    beta[1] = e1 * inv;
}

__global__ void zero_wsum_k(float* w) {
    if (threadIdx.x < 4) w[threadIdx.x] = 0.f;
}

// h[n,:] = beta0*z[n,0,:] + beta1*z[n,1,:]   (iteration 1 only)
__global__ void combine_k(const float* __restrict__ z, const float* __restrict__ beta,
                          float* __restrict__ h, int n) {
    int t = blockIdx.x * blockDim.x + threadIdx.x;
    if (t >= n * 16) return;
    int node = t >> 4;
    int c = t & 15;
    float b0 = beta[0], b1 = beta[1];
    float4 z0 = ((const float4*)z)[node * 32 + c];
    float4 z1 = ((const float4*)z)[node * 32 + 16 + c];
    float4 r;
    r.x = fmaf(b0, z0.x, b1 * z1.x);
    r.y = fmaf(b0, z0.y, b1 * z1.y);
    r.z = fmaf(b0, z0.z, b1 * z1.z);
    r.w = fmaf(b0, z0.w, b1 * z1.w);
    ((float4*)h)[t] = r;
}

// epilogue: iter-2 combine fused into the batched gathers
__global__ void out_k(const float* __restrict__ zu, const float* __restrict__ zi,
                      const float* __restrict__ ui, const float* __restrict__ beta,
                      const int* __restrict__ uidx, const int* __restrict__ iidx,
                      const int* __restrict__ nidx, float* __restrict__ out) {
    int t = blockIdx.x * blockDim.x + threadIdx.x;
    if (t >= B_N * 16) return;
    int b = t >> 4;
    int c = t & 15;
    const float4* zu4 = (const float4*)zu;
    const float4* zi4 = (const float4*)zi;
    const float4* ui4 = (const float4*)ui;
    float4* o4 = (float4*)out;
    float bU0 = beta[0], bU1 = beta[1], bI0 = beta[2], bI1 = beta[3];

    {
        int u = uidx[b];
        float4 z0 = zu4[u * 32 + c];
        float4 z1 = zu4[u * 32 + 16 + c];
        float4 g = ui4[u * 16 + c];
        float4 r;
        r.x = 0.5f * (fmaf(bU0, z0.x, bU1 * z1.x) + g.x);
        r.y = 0.5f * (fmaf(bU0, z0.y, bU1 * z1.y) + g.y);
        r.z = 0.5f * (fmaf(bU0, z0.z, bU1 * z1.z) + g.z);
        r.w = 0.5f * (fmaf(bU0, z0.w, bU1 * z1.w) + g.w);
        o4[t] = r;
    }
    {
        int it = iidx[b];
        float4 z0 = zi4[it * 32 + c];
        float4 z1 = zi4[it * 32 + 16 + c];
        float4 g = ui4[(U_N + it) * 16 + c];
        float4 r;
        r.x = 0.5f * (fmaf(bI0, z0.x, bI1 * z1.x) + g.x);
        r.y = 0.5f * (fmaf(bI0, z0.y, bI1 * z1.y) + g.y);
        r.z = 0.5f * (fmaf(bI0, z0.z, bI1 * z1.z) + g.z);
        r.w = 0.5f * (fmaf(bI0, z0.w, bI1 * z1.w) + g.w);
        o4[B_N * 16 + t] = r;
    }
    {
        int itn = iidx[nidx[b]];
        float4 z0 = zi4[itn * 32 + c];
        float4 z1 = zi4[itn * 32 + 16 + c];
        float4 g = ui4[(U_N + itn) * 16 + c];
        float4 r;
        r.x = 0.5f * (fmaf(bI0, z0.x, bI1 * z1.x) + g.x);
        r.y = 0.5f * (fmaf(bI0, z0.y, bI1 * z1.y) + g.y);
        r.z = 0.5f * (fmaf(bI0, z0.z, bI1 * z1.z) + g.z);
        r.w = 0.5f * (fmaf(bI0, z0.w, bI1 * z1.w) + g.w);
        o4[2 * B_N * 16 + t] = r;
    }
}

// ---------------------------------------------------------------------------
// Host
// ---------------------------------------------------------------------------
static inline int nblk(long long n) { return (int)((n + 255) / 256); }

extern "C" void kernel_launch(void* const* d_in, const int* in_sizes, int n_in,
                              void* d_out, int out_size) {
    const float* user_feat = (const float*)d_in[0];
    const float* item_feat = (const float*)d_in[1];
    const float* sa_u_W1   = (const float*)d_in[2];
    const float* sa_u_b1   = (const float*)d_in[3];
    const float* sa_u_w2   = (const float*)d_in[4];
    const float* sa_i_W1   = (const float*)d_in[5];
    const float* sa_i_b1   = (const float*)d_in[6];
    const float* sa_i_w2   = (const float*)d_in[7];
    const int*   ui_e      = (const int*)d_in[8];
    const int*   ue1       = (const int*)d_in[9];
    const int*   ue2       = (const int*)d_in[10];
    const int*   ie1       = (const int*)d_in[11];
    const int*   ie2       = (const int*)d_in[12];
    const int*   uidx      = (const int*)d_in[13];
    const int*   iidx      = (const int*)d_in[14];
    const int*   nidx      = (const int*)d_in[15];

    const int Eui = in_sizes[8]  / 2;   // 2,000,000 (row then col)
    const int Eu  = in_sizes[9]  / 2;   //   500,000 (src then dst)
    const int Ei  = in_sizes[11] / 2;   // 1,000,000

    float *ui_a, *ui_b, *hu, *hi, *zu, *zi, *wdst, *wsrc, *wsum, *beta;
    int *ibuf, *S, *csr;
    cudaGetSymbolAddress((void**)&ui_a, g_ui_a);
    cudaGetSymbolAddress((void**)&ui_b, g_ui_b);
    cudaGetSymbolAddress((void**)&hu,   g_hu);
    cudaGetSymbolAddress((void**)&hi,   g_hi);
    cudaGetSymbolAddress((void**)&zu,   g_zu);
    cudaGetSymbolAddress((void**)&zi,   g_zi);
    cudaGetSymbolAddress((void**)&wdst, g_wdst);
    cudaGetSymbolAddress((void**)&wsrc, g_wsrc);
    cudaGetSymbolAddress((void**)&wsum, g_wsum);
    cudaGetSymbolAddress((void**)&beta, g_beta);
    cudaGetSymbolAddress((void**)&ibuf, g_int);
    cudaGetSymbolAddress((void**)&S,    g_S);
    cudaGetSymbolAddress((void**)&csr,  g_csr);

    int* deg  = ibuf + OFF_DEG;
    int* cnt  = ibuf + OFF_CNT;
    int* dout = ibuf + OFF_DOUT;
    int* part = ibuf + OFF_PART;

    const int T = 256;

    // ---- zero int scratch ----
    zero_i4_k<<<nblk(INT_TOT / 4), T>>>((int4*)ibuf, INT_TOT / 4);

    // ---- init features ----
    init_k<<<nblk((long long)N_N * 16), T>>>((const float4*)user_feat,
                                             (const float4*)item_feat,
                                             (float4*)ui_a, (float4*)hu, (float4*)hi);

    // ---- degree counts ----
    cnt_k<<<nblk(Eui), T>>>(ui_e,       Eui, deg + RB_GCN);
    cnt_k<<<nblk(Eu),  T>>>(ue1 + Eu,   Eu,  deg + RB_U1);
    cnt_k<<<nblk(Eu),  T>>>(ue2 + Eu,   Eu,  deg + RB_U2);
    cnt_k<<<nblk(Ei),  T>>>(ie1 + Ei,   Ei,  deg + RB_I1);
    cnt_k<<<nblk(Ei),  T>>>(ie2 + Ei,   Ei,  deg + RB_I2);
    cnt_k<<<nblk(Eu),  T>>>(ue1,        Eu,  dout + 0);
    cnt_k<<<nblk(Eu),  T>>>(ue2,        Eu,  dout + U_N);
    cnt_k<<<nblk(Ei),  T>>>(ie1,        Ei,  dout + 2 * U_N);
    cnt_k<<<nblk(Ei),  T>>>(ie2,        Ei,  dout + 2 * U_N + I_N);

    // ---- global exclusive scan -> CSR row offsets ----
    const int nchunks = (NSCAN + 2047) / 2048;  // 220 <= 256
    scan1_k<<<nchunks, T>>>(deg, NSCAN, S, part);
    scan2_k<<<1, 256>>>(part, nchunks);
    scan3_k<<<nblk(NSCAN), T>>>(S, part, NSCAN);

    // ---- normalization weights ----
    weights_k<<<nblk(NTOT), T>>>(deg, dout, wdst, wsrc);

    // ---- CSR fill ----
    fill_k<<<nblk(Eui), T>>>(ui_e + Eui, ui_e,     Eui, S, RB_GCN, cnt, csr);
    fill_k<<<nblk(Eu),  T>>>(ue1,        ue1 + Eu, Eu,  S, RB_U1,  cnt, csr);
    fill_k<<<nblk(Eu),  T>>>(ue2,        ue2 + Eu, Eu,  S, RB_U2,  cnt, csr);
    fill_k<<<nblk(Ei),  T>>>(ie1,        ie1 + Ei, Ei,  S, RB_I1,  cnt, csr);
    fill_k<<<nblk(Ei),  T>>>(ie2,        ie2 + Ei, Ei,  S, RB_I2,  cnt, csr);

    // attention grids: 16-row tiles, 8 warps/block
    const int ntu = (2 * U_N) / 16, blk_u = (ntu + 7) / 8;
    const int nti = (2 * I_N) / 16, blk_i = (nti + 7) / 8;

    // ---- 2 propagation iterations ----
    const float* ui_in = ui_a;
    float* ui_out = ui_b;
    for (int iter = 0; iter < 2; ++iter) {
        pull_k<<<nblk((long long)N_N * 32), T>>>(S + RB_GCN, csr, wdst + RB_GCN,
                                                 wdst + RB_GCN, ui_in, ui_out,
                                                 N_N, 64, 0);
        pull_k<<<nblk((long long)U_N * 32), T>>>(S + RB_U1, csr, wsrc + 0,
                                                 wdst + RB_U1, hu, zu, U_N, 128, 0);
        pull_k<<<nblk((long long)U_N * 32), T>>>(S + RB_U2, csr, wsrc + U_N,
                                                 wdst + RB_U2, hu, zu, U_N, 128, 64);
        pull_k<<<nblk((long long)I_N * 32), T>>>(S + RB_I1, csr, wsrc + 2 * U_N,
                                                 wdst + RB_I1, hi, zi, I_N, 128, 0);
        pull_k<<<nblk((long long)I_N * 32), T>>>(S + RB_I2, csr, wsrc + 2 * U_N + I_N,
                                                 wdst + RB_I2, hi, zi, I_N, 128, 64);

        zero_wsum_k<<<1, 32>>>(wsum);
        han_attn_k<<<blk_u, 256>>>(zu, U_N, sa_u_W1, sa_u_b1, sa_u_w2, wsum + 0);
        beta_k<<<1, 1>>>(wsum + 0, 1.0f / U_N, beta + 0);
        han_attn_k<<<blk_i, 256>>>(zi, I_N, sa_i_W1, sa_i_b1, sa_i_w2, wsum + 2);
        beta_k<<<1, 1>>>(wsum + 2, 1.0f / I_N, beta + 2);

        if (iter == 0) {
            combine_k<<<nblk((long long)U_N * 16), T>>>(zu, beta + 0, hu, U_N);
            combine_k<<<nblk((long long)I_N * 16), T>>>(zi, beta + 2, hi, I_N);
        }

        const float* tmp = ui_in;
        ui_in = ui_out;
        ui_out = (float*)tmp;
    }

    // ---- epilogue ----
    out_k<<<nblk((long long)B_N * 16), T>>>(zu, zi, ui_in, beta,
                                            uidx, iidx, nidx, (float*)d_out);
}